// round 3
// baseline (speedup 1.0000x reference)
#include <cuda_runtime.h>
#include <math.h>

#define B_    32
#define H_    6
#define W_    2400
#define C_    64
#define OV_   4
#define G_    3
#define NVQ_  6
#define K_    1024
#define D_    8
#define FIX_  384
#define GD_   512
#define T_    600
#define NPG   (B_*T_)              // 19200
#define NPTS  (G_*NPG)             // 57600
#define ZQ_SIZE  (B_*H_*W_*C_)     // 29491200
#define IDX_SIZE (B_*NVQ_*G_*T_)   // 345600
#define RVQ_BLOCKS (NPTS/32)       // 1800

__device__ float g_en2[G_*NVQ_*K_*D_];   // pair-packed normalized codebooks
__device__ float g_zd [G_*NPG*D_];
__device__ float g_zqd[G_*NPG*D_];
__device__ float g_partial[RVQ_BLOCKS];

// ---------------------------------------------------------------------------
// K1: normalize codebook rows AND repack pair-interleaved:
// pair j (k=2j,2j+1), dim d -> g_en2[gi*8192 + j*16 + d*2 + (k&1)]
// ---------------------------------------------------------------------------
__global__ void k_norm(const float* __restrict__ cb) {
    int r = blockIdx.x * blockDim.x + threadIdx.x;
    if (r >= G_*NVQ_*K_) return;
    const float* src = cb + (size_t)r * D_;
    float v[8]; float ss = 0.f;
#pragma unroll
    for (int d = 0; d < 8; d++) { v[d] = src[d]; ss = fmaf(v[d], v[d], ss); }
    float inv = 1.0f / fmaxf(sqrtf(ss), 1e-12f);
    int gi = r >> 10, k = r & 1023;
    int j = k >> 1, half = k & 1;
    float* dst = g_en2 + (size_t)gi*(K_*D_) + j*16 + half;
#pragma unroll
    for (int d = 0; d < 8; d++) dst[d*2] = v[d] * inv;
}

// ---------------------------------------------------------------------------
// K2: pre_process fused with proj_down. 4 accumulator chains, float4 z loads.
// ---------------------------------------------------------------------------
#define SZ_STRIDE 1540
#define PD_STRIDE 520
#define K2_SMEM   ((8*SZ_STRIDE + 24*PD_STRIDE) * 4)

__global__ void k_down(const float* __restrict__ ze, const float* __restrict__ pd) {
    extern __shared__ float sm[];
    float* sZ  = sm;
    float* sPD = sm + 8*SZ_STRIDE;
    int bid  = blockIdx.x;
    int b    = bid / (T_/8);
    int tblk = bid % (T_/8);
    int t0   = tblk * 8;
    int w0   = t0 * 4;
    int tid  = threadIdx.x;

    for (int idx = tid; idx < G_*D_*GD_; idx += 256) {
        int gd = idx >> 9, j = idx & 511;
        sPD[gd*PD_STRIDE + j] = pd[idx];
    }
#pragma unroll
    for (int h = 0; h < 6; h++) {
        const float4* src = (const float4*)(ze + ((size_t)(b*H_ + h)*W_ + w0) * C_);
        for (int e4 = tid; e4 < 32*16; e4 += 256) {
            float4 zv = src[e4];
            int e  = e4 * 4;
            int wl = e >> 6, c = e & 63;
            int tl = wl >> 2, o = wl & 3;
            float* dst = sZ + tl*SZ_STRIDE + o*FIX_ + c*6 + h;
            dst[0]  = zv.x; dst[6]  = zv.y;
            dst[12] = zv.z; dst[18] = zv.w;
        }
    }
    __syncthreads();

    if (tid < 192) {
        int gd = tid >> 3;
        int tl = tid & 7;
        int g  = gd >> 3, d = gd & 7;
        const float4* zr = (const float4*)(sZ + tl*SZ_STRIDE + g*GD_);
        const float4* pr = (const float4*)(sPD + gd*PD_STRIDE);
        float a0 = 0.f, a1 = 0.f, a2 = 0.f, a3 = 0.f;
#pragma unroll 8
        for (int j = 0; j < 128; j += 2) {
            float4 z0 = zr[j],   p0 = pr[j];
            float4 z1 = zr[j+1], p1 = pr[j+1];
            a0 = fmaf(z0.x, p0.x, a0); a1 = fmaf(z0.y, p0.y, a1);
            a2 = fmaf(z0.z, p0.z, a2); a3 = fmaf(z0.w, p0.w, a3);
            a0 = fmaf(z1.x, p1.x, a0); a1 = fmaf(z1.y, p1.y, a1);
            a2 = fmaf(z1.z, p1.z, a2); a3 = fmaf(z1.w, p1.w, a3);
        }
        g_zd[((size_t)g*NPG + b*T_ + t0 + tl)*D_ + d] = (a0 + a1) + (a2 + a3);
    }
}

// ---------------------------------------------------------------------------
// K3: residual VQ. One warp per block (32 points), no smem, no barriers.
// Codebook read via uniform-address LDG (L1-resident 32KB per stream).
// f32x2 FFMA2 over codeword pairs; single best-update per pair via fmaxf.
// ---------------------------------------------------------------------------
__global__ void __launch_bounds__(32) k_rvq(float* __restrict__ out_codes) {
    int p = blockIdx.x * 32 + threadIdx.x;
    int g = p / NPG;
    int pl = p - g*NPG;
    int b = pl / T_, t = pl - b*T_;

    const float4* zd4 = (const float4*)g_zd;
    float4 rl = zd4[(size_t)p*2];
    float4 rh = zd4[(size_t)p*2 + 1];
    float r[8] = { rl.x, rl.y, rl.z, rl.w, rh.x, rh.y, rh.z, rh.w };
    float q[8] = { 0,0,0,0,0,0,0,0 };
    float sse = 0.f;
    int codes[NVQ_];

    for (int i = 0; i < NVQ_; i++) {
        const ulonglong2* eb = (const ulonglong2*)(g_en2 + (size_t)(g*NVQ_ + i)*(K_*D_));

        unsigned long long r2[8];
#pragma unroll
        for (int d = 0; d < 8; d++)
            asm("mov.b64 %0, {%1, %1};" : "=l"(r2[d]) : "f"(r[d]));

        float best = -3.0e38f; int bk = 0;
#pragma unroll 4
        for (int j = 0; j < K_/2; j++) {
            ulonglong2 ea = __ldg(eb + j*4 + 0);
            ulonglong2 e2 = __ldg(eb + j*4 + 1);
            ulonglong2 ec = __ldg(eb + j*4 + 2);
            ulonglong2 ed = __ldg(eb + j*4 + 3);
            unsigned long long acc;
            asm("mul.rn.f32x2 %0, %1, %2;"     : "=l"(acc) : "l"(r2[0]), "l"(ea.x));
            asm("fma.rn.f32x2 %0, %1, %2, %0;" : "+l"(acc) : "l"(r2[1]), "l"(ea.y));
            asm("fma.rn.f32x2 %0, %1, %2, %0;" : "+l"(acc) : "l"(r2[2]), "l"(e2.x));
            asm("fma.rn.f32x2 %0, %1, %2, %0;" : "+l"(acc) : "l"(r2[3]), "l"(e2.y));
            asm("fma.rn.f32x2 %0, %1, %2, %0;" : "+l"(acc) : "l"(r2[4]), "l"(ec.x));
            asm("fma.rn.f32x2 %0, %1, %2, %0;" : "+l"(acc) : "l"(r2[5]), "l"(ec.y));
            asm("fma.rn.f32x2 %0, %1, %2, %0;" : "+l"(acc) : "l"(r2[6]), "l"(ed.x));
            asm("fma.rn.f32x2 %0, %1, %2, %0;" : "+l"(acc) : "l"(r2[7]), "l"(ed.y));
            float lo, hi;
            asm("mov.b64 {%0, %1}, %2;" : "=f"(lo), "=f"(hi) : "l"(acc));
            float m = fmaxf(lo, hi);
            int sel = (hi > lo) ? (2*j + 1) : (2*j);   // tie -> even k (first)
            if (m > best) { best = m; bk = sel; }      // strict -> first pair wins
        }
        codes[i] = bk;

        const float2* ep = (const float2*)eb + (size_t)(bk >> 1)*8;
        int hsel = bk & 1;
        float ss = 0.f;
#pragma unroll
        for (int d = 0; d < 8; d++) {
            float2 pr = __ldg(ep + d);
            float ev = hsel ? pr.y : pr.x;
            r[d] -= ev; q[d] += ev;
            ss = fmaf(r[d], r[d], ss);
        }
        sse += ss;
    }

    float4* zq4 = (float4*)g_zqd;
    zq4[(size_t)p*2]     = make_float4(q[0], q[1], q[2], q[3]);
    zq4[(size_t)p*2 + 1] = make_float4(q[4], q[5], q[6], q[7]);
#pragma unroll
    for (int i = 0; i < NVQ_; i++)
        out_codes[((size_t)(b*NVQ_ + i)*G_ + g)*T_ + t] = (float)codes[i];

#pragma unroll
    for (int off = 16; off > 0; off >>= 1)
        sse += __shfl_down_sync(0xffffffffu, sse, off);
    if (threadIdx.x == 0) g_partial[blockIdx.x] = sse;
}

// ---------------------------------------------------------------------------
// K4: proj_up fused with post_process (unchanged from R2).
// ---------------------------------------------------------------------------
#define TT 25
__global__ void __launch_bounds__(256) k_up(const float* __restrict__ pu, float* __restrict__ out) {
    __shared__ float sZ[G_*TT*D_];
    int bid  = blockIdx.x;
    int b    = bid / (T_/TT);
    int tile = bid % (T_/TT);
    int t0   = tile * TT;
    int tid  = threadIdx.x;

    for (int idx = tid; idx < G_*TT*D_; idx += 256) {
        int g  = idx / (TT*D_);
        int rr = idx % (TT*D_);
        sZ[idx] = g_zqd[((size_t)g*NPG + b*T_ + t0)*D_ + rr];
    }
    __syncthreads();

    int wid = tid >> 5, lane = tid & 31;
    for (int task = wid; task < 48; task += 8) {
        int o   = task / 12;
        int rem = task % 12;
        int h   = rem >> 1;
        int ch  = rem & 1;
        int c   = ch*32 + lane;
        int pp  = o*FIX_ + c*6 + h;
        int g   = pp >> 9;
        const float4* pu4 = (const float4*)pu + (size_t)pp*2;
        float4 pl = __ldg(pu4), ph = __ldg(pu4 + 1);
        float* op = out + ((size_t)(b*H_ + h)*W_ + 4*t0 + o)*C_ + c;
        const float4* zb = (const float4*)(sZ + g*(TT*D_));
#pragma unroll 5
        for (int tl = 0; tl < TT; tl++) {
            float4 zl = zb[tl*2], zh = zb[tl*2 + 1];
            float s0 = zl.x*pl.x, s1 = zl.y*pl.y;
            s0 = fmaf(zl.z, pl.z, s0); s1 = fmaf(zl.w, pl.w, s1);
            s0 = fmaf(zh.x, ph.x, s0); s1 = fmaf(zh.y, ph.y, s1);
            s0 = fmaf(zh.z, ph.z, s0); s1 = fmaf(zh.w, ph.w, s1);
            op[(size_t)tl*4*C_] = s0 + s1;
        }
    }
}

// ---------------------------------------------------------------------------
// K5: final deterministic loss reduction over 1800 partials.
// ---------------------------------------------------------------------------
__global__ void k_final(float* __restrict__ d_out) {
    __shared__ float s[512];
    int tid = threadIdx.x;
    float v = 0.f;
    for (int idx = tid; idx < RVQ_BLOCKS; idx += 512) v += g_partial[idx];
    s[tid] = v; __syncthreads();
    for (int off = 256; off > 0; off >>= 1) {
        if (tid < off) s[tid] += s[tid + off];
        __syncthreads();
    }
    if (tid == 0) {
        float loss = s[0] / (float)(G_ * B_ * T_ * D_);
        d_out[ZQ_SIZE + IDX_SIZE]     = loss;
        d_out[ZQ_SIZE + IDX_SIZE + 1] = loss;
    }
}

// ---------------------------------------------------------------------------
extern "C" void kernel_launch(void* const* d_in, const int* in_sizes, int n_in,
                              void* d_out, int out_size) {
    const float* z_e = (const float*)d_in[0];
    const float* pd  = (const float*)d_in[1];
    const float* pu  = (const float*)d_in[2];
    const float* cb  = (const float*)d_in[3];
    float* out = (float*)d_out;

    cudaFuncSetAttribute(k_down, cudaFuncAttributeMaxDynamicSharedMemorySize, K2_SMEM);

    k_norm<<<(G_*NVQ_*K_ + 255)/256, 256>>>(cb);
    k_down<<<B_*(T_/8), 256, K2_SMEM>>>(z_e, pd);
    k_rvq<<<RVQ_BLOCKS, 32>>>(out + ZQ_SIZE);
    k_up<<<B_*(T_/TT), 256>>>(pu, out);
    k_final<<<1, 512>>>(out);
}

// round 4
// speedup vs baseline: 2.3718x; 2.3718x over previous
#include <cuda_runtime.h>
#include <math.h>

#define B_    32
#define H_    6
#define W_    2400
#define C_    64
#define OV_   4
#define G_    3
#define NVQ_  6
#define K_    1024
#define D_    8
#define FIX_  384
#define GD_   512
#define T_    600
#define NPG   (B_*T_)              // 19200
#define NPTS  (G_*NPG)             // 57600
#define ZQ_SIZE  (B_*H_*W_*C_)     // 29491200
#define IDX_SIZE (B_*NVQ_*G_*T_)   // 345600
#define RVQ_BLOCKS 900             // 64 points per block

__device__ float g_en2 [G_*NVQ_*K_*D_];  // pair-packed (for gather)
__device__ float g_en2s[G_*NVQ_*K_*D_];  // split-layout [j][q][s] (for smem scan)
__device__ float g_zd [G_*NPG*D_];
__device__ float g_zqd[G_*NPG*D_];
__device__ float g_partial[RVQ_BLOCKS];

// ---------------------------------------------------------------------------
// K1: normalize codebook rows; write BOTH layouts.
// pair layout:  g_en2 [gi*8192 + j*16 + d*2 + half]          (j = k>>1, half = k&1)
// split layout: g_en2s[gi*8192 + jl*64 + q*16 + s*4 + pos]   (s = k>>8, jl = (k&255)>>1,
//                                                             q = d>>1, pos = (d&1)*2 + half)
// ---------------------------------------------------------------------------
__global__ void k_norm(const float* __restrict__ cb) {
    int r = blockIdx.x * blockDim.x + threadIdx.x;
    if (r >= G_*NVQ_*K_) return;
    const float* src = cb + (size_t)r * D_;
    float v[8]; float ss = 0.f;
#pragma unroll
    for (int d = 0; d < 8; d++) { v[d] = src[d]; ss = fmaf(v[d], v[d], ss); }
    float inv = 1.0f / fmaxf(sqrtf(ss), 1e-12f);
    int gi = r >> 10, k = r & 1023;
    int j = k >> 1, half = k & 1;
    int s = k >> 8, jl = (k & 255) >> 1;
    float* d1 = g_en2  + (size_t)gi*(K_*D_) + j*16 + half;
    float* d2 = g_en2s + (size_t)gi*(K_*D_) + jl*64 + s*4 + half;
#pragma unroll
    for (int d = 0; d < 8; d++) {
        float e = v[d] * inv;
        d1[d*2] = e;
        d2[(d >> 1)*16 + (d & 1)*2] = e;
    }
}

// ---------------------------------------------------------------------------
// K2: pre_process fused with proj_down (unchanged from R3).
// ---------------------------------------------------------------------------
#define SZ_STRIDE 1540
#define PD_STRIDE 520
#define K2_SMEM   ((8*SZ_STRIDE + 24*PD_STRIDE) * 4)

__global__ void k_down(const float* __restrict__ ze, const float* __restrict__ pd) {
    extern __shared__ float sm[];
    float* sZ  = sm;
    float* sPD = sm + 8*SZ_STRIDE;
    int bid  = blockIdx.x;
    int b    = bid / (T_/8);
    int tblk = bid % (T_/8);
    int t0   = tblk * 8;
    int w0   = t0 * 4;
    int tid  = threadIdx.x;

    for (int idx = tid; idx < G_*D_*GD_; idx += 256) {
        int gd = idx >> 9, j = idx & 511;
        sPD[gd*PD_STRIDE + j] = pd[idx];
    }
#pragma unroll
    for (int h = 0; h < 6; h++) {
        const float4* src = (const float4*)(ze + ((size_t)(b*H_ + h)*W_ + w0) * C_);
        for (int e4 = tid; e4 < 32*16; e4 += 256) {
            float4 zv = src[e4];
            int e  = e4 * 4;
            int wl = e >> 6, c = e & 63;
            int tl = wl >> 2, o = wl & 3;
            float* dst = sZ + tl*SZ_STRIDE + o*FIX_ + c*6 + h;
            dst[0]  = zv.x; dst[6]  = zv.y;
            dst[12] = zv.z; dst[18] = zv.w;
        }
    }
    __syncthreads();

    if (tid < 192) {
        int gd = tid >> 3;
        int tl = tid & 7;
        int g  = gd >> 3, d = gd & 7;
        const float4* zr = (const float4*)(sZ + tl*SZ_STRIDE + g*GD_);
        const float4* pr = (const float4*)(sPD + gd*PD_STRIDE);
        float a0 = 0.f, a1 = 0.f, a2 = 0.f, a3 = 0.f;
#pragma unroll 8
        for (int j = 0; j < 128; j += 2) {
            float4 z0 = zr[j],   p0 = pr[j];
            float4 z1 = zr[j+1], p1 = pr[j+1];
            a0 = fmaf(z0.x, p0.x, a0); a1 = fmaf(z0.y, p0.y, a1);
            a2 = fmaf(z0.z, p0.z, a2); a3 = fmaf(z0.w, p0.w, a3);
            a0 = fmaf(z1.x, p1.x, a0); a1 = fmaf(z1.y, p1.y, a1);
            a2 = fmaf(z1.z, p1.z, a2); a3 = fmaf(z1.w, p1.w, a3);
        }
        g_zd[((size_t)g*NPG + b*T_ + t0 + tl)*D_ + d] = (a0 + a1) + (a2 + a3);
    }
}

// ---------------------------------------------------------------------------
// K3: residual VQ. Block = 64 points x 4 k-splits (128 threads).
// Thread = (2 points, 1 split of 256 codewords). Codebook in smem, split
// layout: one 64B row serves all 4 splits conflict-free (broadcast).
// Cross-split argmax via 64-bit key shfl (exact first-max tie rule).
// ---------------------------------------------------------------------------
__device__ __forceinline__ int combine4(float best, int bk) {
    unsigned bits = __float_as_uint(best);
    unsigned su = bits ^ (unsigned)(((int)bits >> 31) | 0x80000000);
    unsigned long long key = ((unsigned long long)su << 10) | (unsigned)(1023 - bk);
    unsigned long long o = __shfl_xor_sync(0xffffffffu, key, 1);
    key = (o > key) ? o : key;
    o = __shfl_xor_sync(0xffffffffu, key, 2);
    key = (o > key) ? o : key;
    return 1023 - (int)(key & 1023u);
}

__global__ void __launch_bounds__(128) k_rvq(float* __restrict__ out_codes) {
    __shared__ float sE[K_*D_];   // 32 KB, split layout for current stream
    __shared__ float sWarp[4];
    int bid = blockIdx.x;
    int g   = bid / (RVQ_BLOCKS/G_);       // 300 blocks per group
    int lb  = bid % (RVQ_BLOCKS/G_);
    int tid = threadIdx.x;
    int pp  = tid >> 2;                    // 0..31
    int s   = tid & 3;                     // split
    int pA  = g*NPG + lb*64 + pp*2;
    int pB  = pA + 1;

    const float4* zd4 = (const float4*)g_zd;
    float4 al = zd4[(size_t)pA*2], ah = zd4[(size_t)pA*2+1];
    float4 bl = zd4[(size_t)pB*2], bh = zd4[(size_t)pB*2+1];
    float rA[8] = { al.x, al.y, al.z, al.w, ah.x, ah.y, ah.z, ah.w };
    float rB[8] = { bl.x, bl.y, bl.z, bl.w, bh.x, bh.y, bh.z, bh.w };
    float qA[8] = {0,0,0,0,0,0,0,0}, qB[8] = {0,0,0,0,0,0,0,0};
    float sse = 0.f;
    int codesA[NVQ_], codesB[NVQ_];

    for (int i = 0; i < NVQ_; i++) {
        __syncthreads();
        {
            const float4* src = (const float4*)(g_en2s + (size_t)(g*NVQ_ + i)*(K_*D_));
            float4* dst = (float4*)sE;
#pragma unroll
            for (int j = 0; j < 16; j++) dst[tid + j*128] = src[tid + j*128];
        }
        __syncthreads();

        unsigned long long r2A[8], r2B[8];
#pragma unroll
        for (int d = 0; d < 8; d++) {
            asm("mov.b64 %0, {%1, %1};" : "=l"(r2A[d]) : "f"(rA[d]));
            asm("mov.b64 %0, {%1, %1};" : "=l"(r2B[d]) : "f"(rB[d]));
        }

        const ulonglong2* e2 = (const ulonglong2*)sE;
        float bestA = -3.0e38f, bestB = -3.0e38f;
        int bkA = 0, bkB = 0;
#pragma unroll 4
        for (int j = 0; j < 128; j++) {
            int base = j*16 + s;
            ulonglong2 c0 = e2[base];
            ulonglong2 c1 = e2[base + 4];
            ulonglong2 c2 = e2[base + 8];
            ulonglong2 c3 = e2[base + 12];
            unsigned long long aA, aB;
            asm("mul.rn.f32x2 %0, %1, %2;"     : "=l"(aA) : "l"(r2A[0]), "l"(c0.x));
            asm("fma.rn.f32x2 %0, %1, %2, %0;" : "+l"(aA) : "l"(r2A[1]), "l"(c0.y));
            asm("fma.rn.f32x2 %0, %1, %2, %0;" : "+l"(aA) : "l"(r2A[2]), "l"(c1.x));
            asm("fma.rn.f32x2 %0, %1, %2, %0;" : "+l"(aA) : "l"(r2A[3]), "l"(c1.y));
            asm("fma.rn.f32x2 %0, %1, %2, %0;" : "+l"(aA) : "l"(r2A[4]), "l"(c2.x));
            asm("fma.rn.f32x2 %0, %1, %2, %0;" : "+l"(aA) : "l"(r2A[5]), "l"(c2.y));
            asm("fma.rn.f32x2 %0, %1, %2, %0;" : "+l"(aA) : "l"(r2A[6]), "l"(c3.x));
            asm("fma.rn.f32x2 %0, %1, %2, %0;" : "+l"(aA) : "l"(r2A[7]), "l"(c3.y));
            asm("mul.rn.f32x2 %0, %1, %2;"     : "=l"(aB) : "l"(r2B[0]), "l"(c0.x));
            asm("fma.rn.f32x2 %0, %1, %2, %0;" : "+l"(aB) : "l"(r2B[1]), "l"(c0.y));
            asm("fma.rn.f32x2 %0, %1, %2, %0;" : "+l"(aB) : "l"(r2B[2]), "l"(c1.x));
            asm("fma.rn.f32x2 %0, %1, %2, %0;" : "+l"(aB) : "l"(r2B[3]), "l"(c1.y));
            asm("fma.rn.f32x2 %0, %1, %2, %0;" : "+l"(aB) : "l"(r2B[4]), "l"(c2.x));
            asm("fma.rn.f32x2 %0, %1, %2, %0;" : "+l"(aB) : "l"(r2B[5]), "l"(c2.y));
            asm("fma.rn.f32x2 %0, %1, %2, %0;" : "+l"(aB) : "l"(r2B[6]), "l"(c3.x));
            asm("fma.rn.f32x2 %0, %1, %2, %0;" : "+l"(aB) : "l"(r2B[7]), "l"(c3.y));
            float lo, hi;
            asm("mov.b64 {%0, %1}, %2;" : "=f"(lo), "=f"(hi) : "l"(aA));
            float m = fmaxf(lo, hi);
            int kk = s*256 + 2*j + ((hi > lo) ? 1 : 0);
            if (m > bestA) { bestA = m; bkA = kk; }
            asm("mov.b64 {%0, %1}, %2;" : "=f"(lo), "=f"(hi) : "l"(aB));
            m = fmaxf(lo, hi);
            kk = s*256 + 2*j + ((hi > lo) ? 1 : 0);
            if (m > bestB) { bestB = m; bkB = kk; }
        }
        int kA = combine4(bestA, bkA);
        int kB = combine4(bestB, bkB);
        codesA[i] = kA; codesB[i] = kB;

        const float2* gbase = (const float2*)(g_en2 + (size_t)(g*NVQ_ + i)*(K_*D_));
        const float2* epA = gbase + (size_t)(kA >> 1)*8;
        const float2* epB = gbase + (size_t)(kB >> 1)*8;
        int hA = kA & 1, hB = kB & 1;
        float ssA = 0.f, ssB = 0.f;
#pragma unroll
        for (int d = 0; d < 8; d++) {
            float2 ca = __ldg(epA + d);
            float ev = hA ? ca.y : ca.x;
            rA[d] -= ev; qA[d] += ev;
            ssA = fmaf(rA[d], rA[d], ssA);
            float2 cb2 = __ldg(epB + d);
            ev = hB ? cb2.y : cb2.x;
            rB[d] -= ev; qB[d] += ev;
            ssB = fmaf(rB[d], rB[d], ssB);
        }
        sse += ssA + ssB;
    }

    if (s == 0) {
        float4* zq4 = (float4*)g_zqd;
        zq4[(size_t)pA*2]     = make_float4(qA[0], qA[1], qA[2], qA[3]);
        zq4[(size_t)pA*2 + 1] = make_float4(qA[4], qA[5], qA[6], qA[7]);
        zq4[(size_t)pB*2]     = make_float4(qB[0], qB[1], qB[2], qB[3]);
        zq4[(size_t)pB*2 + 1] = make_float4(qB[4], qB[5], qB[6], qB[7]);
        int plA = pA - g*NPG, plB = pB - g*NPG;
        int bA = plA / T_, tA = plA % T_;
        int bB = plB / T_, tB = plB % T_;
#pragma unroll
        for (int i = 0; i < NVQ_; i++) {
            out_codes[((size_t)(bA*NVQ_ + i)*G_ + g)*T_ + tA] = (float)codesA[i];
            out_codes[((size_t)(bB*NVQ_ + i)*G_ + g)*T_ + tB] = (float)codesB[i];
        }
    }

    float c = (s == 0) ? sse : 0.f;
#pragma unroll
    for (int off = 16; off > 0; off >>= 1)
        c += __shfl_down_sync(0xffffffffu, c, off);
    int lane = tid & 31, wid = tid >> 5;
    if (lane == 0) sWarp[wid] = c;
    __syncthreads();
    if (tid == 0)
        g_partial[bid] = (sWarp[0] + sWarp[1]) + (sWarp[2] + sWarp[3]);
}

// ---------------------------------------------------------------------------
// K4: proj_up fused with post_process (unchanged).
// ---------------------------------------------------------------------------
#define TT 25
__global__ void __launch_bounds__(256) k_up(const float* __restrict__ pu, float* __restrict__ out) {
    __shared__ float sZ[G_*TT*D_];
    int bid  = blockIdx.x;
    int b    = bid / (T_/TT);
    int tile = bid % (T_/TT);
    int t0   = tile * TT;
    int tid  = threadIdx.x;

    for (int idx = tid; idx < G_*TT*D_; idx += 256) {
        int g  = idx / (TT*D_);
        int rr = idx % (TT*D_);
        sZ[idx] = g_zqd[((size_t)g*NPG + b*T_ + t0)*D_ + rr];
    }
    __syncthreads();

    int wid = tid >> 5, lane = tid & 31;
    for (int task = wid; task < 48; task += 8) {
        int o   = task / 12;
        int rem = task % 12;
        int h   = rem >> 1;
        int ch  = rem & 1;
        int c   = ch*32 + lane;
        int pp  = o*FIX_ + c*6 + h;
        int g   = pp >> 9;
        const float4* pu4 = (const float4*)pu + (size_t)pp*2;
        float4 pl = __ldg(pu4), ph = __ldg(pu4 + 1);
        float* op = out + ((size_t)(b*H_ + h)*W_ + 4*t0 + o)*C_ + c;
        const float4* zb = (const float4*)(sZ + g*(TT*D_));
#pragma unroll 5
        for (int tl = 0; tl < TT; tl++) {
            float4 zl = zb[tl*2], zh = zb[tl*2 + 1];
            float s0 = zl.x*pl.x, s1 = zl.y*pl.y;
            s0 = fmaf(zl.z, pl.z, s0); s1 = fmaf(zl.w, pl.w, s1);
            s0 = fmaf(zh.x, ph.x, s0); s1 = fmaf(zh.y, ph.y, s1);
            s0 = fmaf(zh.z, ph.z, s0); s1 = fmaf(zh.w, ph.w, s1);
            op[(size_t)tl*4*C_] = s0 + s1;
        }
    }
}

// ---------------------------------------------------------------------------
// K5: final deterministic loss reduction.
// ---------------------------------------------------------------------------
__global__ void k_final(float* __restrict__ d_out) {
    __shared__ float s[512];
    int tid = threadIdx.x;
    float v = 0.f;
    for (int idx = tid; idx < RVQ_BLOCKS; idx += 512) v += g_partial[idx];
    s[tid] = v; __syncthreads();
    for (int off = 256; off > 0; off >>= 1) {
        if (tid < off) s[tid] += s[tid + off];
        __syncthreads();
    }
    if (tid == 0) {
        float loss = s[0] / (float)(G_ * B_ * T_ * D_);
        d_out[ZQ_SIZE + IDX_SIZE]     = loss;
        d_out[ZQ_SIZE + IDX_SIZE + 1] = loss;
    }
}

// ---------------------------------------------------------------------------
extern "C" void kernel_launch(void* const* d_in, const int* in_sizes, int n_in,
                              void* d_out, int out_size) {
    const float* z_e = (const float*)d_in[0];
    const float* pd  = (const float*)d_in[1];
    const float* pu  = (const float*)d_in[2];
    const float* cb  = (const float*)d_in[3];
    float* out = (float*)d_out;

    cudaFuncSetAttribute(k_down, cudaFuncAttributeMaxDynamicSharedMemorySize, K2_SMEM);

    k_norm<<<(G_*NVQ_*K_ + 255)/256, 256>>>(cb);
    k_down<<<B_*(T_/8), 256, K2_SMEM>>>(z_e, pd);
    k_rvq<<<RVQ_BLOCKS, 128>>>(out + ZQ_SIZE);
    k_up<<<B_*(T_/TT), 256>>>(pu, out);
    k_final<<<1, 512>>>(out);
}

// round 5
// speedup vs baseline: 2.5739x; 1.0852x over previous
#include <cuda_runtime.h>
#include <math.h>

#define B_    32
#define H_    6
#define W_    2400
#define C_    64
#define OV_   4
#define G_    3
#define NVQ_  6
#define K_    1024
#define D_    8
#define FIX_  384
#define GD_   512
#define T_    600
#define NPG   (B_*T_)              // 19200
#define NPTS  (G_*NPG)             // 57600
#define ZQ_SIZE  (B_*H_*W_*C_)     // 29491200
#define IDX_SIZE (B_*NVQ_*G_*T_)   // 345600
#define RVQ_BLOCKS 900             // 64 points per block, 64 threads

__device__ float g_en2s[G_*NVQ_*K_*D_];  // split layout [jl][q][s][pos]
__device__ float g_zd [G_*NPG*D_];
__device__ float g_zqd[G_*NPG*D_];
__device__ float g_partial[RVQ_BLOCKS];

// ---------------------------------------------------------------------------
// K1: normalize codebook rows, split layout only:
// g_en2s[gi*8192 + jl*64 + (d>>1)*16 + s*4 + (d&1)*2 + half]
//   s = k>>8, jl = (k&255)>>1, half = k&1
// ---------------------------------------------------------------------------
__global__ void k_norm(const float* __restrict__ cb) {
    int r = blockIdx.x * blockDim.x + threadIdx.x;
    if (r >= G_*NVQ_*K_) return;
    const float* src = cb + (size_t)r * D_;
    float v[8]; float ss = 0.f;
#pragma unroll
    for (int d = 0; d < 8; d++) { v[d] = src[d]; ss = fmaf(v[d], v[d], ss); }
    float inv = 1.0f / fmaxf(sqrtf(ss), 1e-12f);
    int gi = r >> 10, k = r & 1023;
    int s = k >> 8, jl = (k & 255) >> 1, half = k & 1;
    float* d2 = g_en2s + (size_t)gi*(K_*D_) + jl*64 + s*4 + half;
#pragma unroll
    for (int d = 0; d < 8; d++)
        d2[(d >> 1)*16 + (d & 1)*2] = v[d] * inv;
}

// ---------------------------------------------------------------------------
// K2: pre_process fused with proj_down (unchanged).
// ---------------------------------------------------------------------------
#define SZ_STRIDE 1540
#define PD_STRIDE 520
#define K2_SMEM   ((8*SZ_STRIDE + 24*PD_STRIDE) * 4)

__global__ void k_down(const float* __restrict__ ze, const float* __restrict__ pd) {
    extern __shared__ float sm[];
    float* sZ  = sm;
    float* sPD = sm + 8*SZ_STRIDE;
    int bid  = blockIdx.x;
    int b    = bid / (T_/8);
    int tblk = bid % (T_/8);
    int t0   = tblk * 8;
    int w0   = t0 * 4;
    int tid  = threadIdx.x;

    for (int idx = tid; idx < G_*D_*GD_; idx += 256) {
        int gd = idx >> 9, j = idx & 511;
        sPD[gd*PD_STRIDE + j] = pd[idx];
    }
#pragma unroll
    for (int h = 0; h < 6; h++) {
        const float4* src = (const float4*)(ze + ((size_t)(b*H_ + h)*W_ + w0) * C_);
        for (int e4 = tid; e4 < 32*16; e4 += 256) {
            float4 zv = src[e4];
            int e  = e4 * 4;
            int wl = e >> 6, c = e & 63;
            int tl = wl >> 2, o = wl & 3;
            float* dst = sZ + tl*SZ_STRIDE + o*FIX_ + c*6 + h;
            dst[0]  = zv.x; dst[6]  = zv.y;
            dst[12] = zv.z; dst[18] = zv.w;
        }
    }
    __syncthreads();

    if (tid < 192) {
        int gd = tid >> 3;
        int tl = tid & 7;
        int g  = gd >> 3, d = gd & 7;
        const float4* zr = (const float4*)(sZ + tl*SZ_STRIDE + g*GD_);
        const float4* pr = (const float4*)(sPD + gd*PD_STRIDE);
        float a0 = 0.f, a1 = 0.f, a2 = 0.f, a3 = 0.f;
#pragma unroll 8
        for (int j = 0; j < 128; j += 2) {
            float4 z0 = zr[j],   p0 = pr[j];
            float4 z1 = zr[j+1], p1 = pr[j+1];
            a0 = fmaf(z0.x, p0.x, a0); a1 = fmaf(z0.y, p0.y, a1);
            a2 = fmaf(z0.z, p0.z, a2); a3 = fmaf(z0.w, p0.w, a3);
            a0 = fmaf(z1.x, p1.x, a0); a1 = fmaf(z1.y, p1.y, a1);
            a2 = fmaf(z1.z, p1.z, a2); a3 = fmaf(z1.w, p1.w, a3);
        }
        g_zd[((size_t)g*NPG + b*T_ + t0 + tl)*D_ + d] = (a0 + a1) + (a2 + a3);
    }
}

// ---------------------------------------------------------------------------
// K3: residual VQ. Block = 64 threads = 16 point-slots x 4 k-splits,
// 4 points per thread (one 64B codebook chunk feeds 4 accumulator chains).
// Residuals live only as packed f32x2. Gather chosen codeword from smem.
// Cross-split argmax: 64-bit key shfl (exact jnp first-max tie rule).
// ---------------------------------------------------------------------------
__device__ __forceinline__ int combine4(float best, int bk) {
    unsigned bits = __float_as_uint(best);
    unsigned su = bits ^ (unsigned)(((int)bits >> 31) | 0x80000000);
    unsigned long long key = ((unsigned long long)su << 10) | (unsigned)(1023 - bk);
    unsigned long long o = __shfl_xor_sync(0xffffffffu, key, 1);
    key = (o > key) ? o : key;
    o = __shfl_xor_sync(0xffffffffu, key, 2);
    key = (o > key) ? o : key;
    return 1023 - (int)(key & 1023u);
}

__global__ void __launch_bounds__(64) k_rvq(float* __restrict__ out_codes) {
    __shared__ float sE[K_*D_];   // 32 KB
    __shared__ float sWarp[2];
    int bid = blockIdx.x;
    int g   = bid / (RVQ_BLOCKS/G_);       // 300 blocks per group
    int lb  = bid % (RVQ_BLOCKS/G_);
    int tid = threadIdx.x;
    int pp  = tid >> 2;                    // 0..15
    int s   = tid & 3;                     // split
    int pl0 = lb*64 + pp*4;                // local point within group
    int p0  = g*NPG + pl0;

    // residuals, packed {r,r} in f32x2
    unsigned long long r2[4][8];
    {
        const float4* zd4 = (const float4*)g_zd;
#pragma unroll
        for (int m = 0; m < 4; m++) {
            float4 lo = zd4[(size_t)(p0+m)*2], hi = zd4[(size_t)(p0+m)*2+1];
            float rv[8] = { lo.x, lo.y, lo.z, lo.w, hi.x, hi.y, hi.z, hi.w };
#pragma unroll
            for (int d = 0; d < 8; d++)
                asm("mov.b64 %0, {%1, %1};" : "=l"(r2[m][d]) : "f"(rv[d]));
        }
    }
    // code output offsets (indices[b, i, g, t])
    int ofs[4];
#pragma unroll
    for (int m = 0; m < 4; m++) {
        int pl = pl0 + m;
        int b = pl / T_, t = pl - b*T_;
        ofs[m] = (b*NVQ_*G_ + g)*T_ + t;
    }

    float sse = 0.f;

    for (int i = 0; i < NVQ_; i++) {
        __syncthreads();
        {
            const float4* src = (const float4*)(g_en2s + (size_t)(g*NVQ_ + i)*(K_*D_));
            float4* dst = (float4*)sE;
#pragma unroll
            for (int j = 0; j < 32; j++) dst[tid + j*64] = src[tid + j*64];
        }
        __syncthreads();

        const ulonglong2* e2 = (const ulonglong2*)sE;
        float best0 = -3.0e38f, best1 = -3.0e38f, best2v = -3.0e38f, best3 = -3.0e38f;
        int bk0 = 0, bk1 = 0, bk2 = 0, bk3 = 0;
#pragma unroll 2
        for (int j = 0; j < 128; j++) {
            int base = j*16 + s;
            ulonglong2 c0 = e2[base];
            ulonglong2 c1 = e2[base + 4];
            ulonglong2 c2 = e2[base + 8];
            ulonglong2 c3 = e2[base + 12];
#define SIM(mm, ACC) \
            asm("mul.rn.f32x2 %0, %1, %2;"     : "=l"(ACC) : "l"(r2[mm][0]), "l"(c0.x)); \
            asm("fma.rn.f32x2 %0, %1, %2, %0;" : "+l"(ACC) : "l"(r2[mm][1]), "l"(c0.y)); \
            asm("fma.rn.f32x2 %0, %1, %2, %0;" : "+l"(ACC) : "l"(r2[mm][2]), "l"(c1.x)); \
            asm("fma.rn.f32x2 %0, %1, %2, %0;" : "+l"(ACC) : "l"(r2[mm][3]), "l"(c1.y)); \
            asm("fma.rn.f32x2 %0, %1, %2, %0;" : "+l"(ACC) : "l"(r2[mm][4]), "l"(c2.x)); \
            asm("fma.rn.f32x2 %0, %1, %2, %0;" : "+l"(ACC) : "l"(r2[mm][5]), "l"(c2.y)); \
            asm("fma.rn.f32x2 %0, %1, %2, %0;" : "+l"(ACC) : "l"(r2[mm][6]), "l"(c3.x)); \
            asm("fma.rn.f32x2 %0, %1, %2, %0;" : "+l"(ACC) : "l"(r2[mm][7]), "l"(c3.y));
            unsigned long long a0, a1, a2, a3;
            SIM(0, a0) SIM(1, a1) SIM(2, a2) SIM(3, a3)
#undef SIM
            float lo, hi, m;
            int cand;
            asm("mov.b64 {%0, %1}, %2;" : "=f"(lo), "=f"(hi) : "l"(a0));
            m = fmaxf(lo, hi); cand = 2*j + ((hi > lo) ? 1 : 0);
            if (m > best0) { best0 = m; bk0 = cand; }
            asm("mov.b64 {%0, %1}, %2;" : "=f"(lo), "=f"(hi) : "l"(a1));
            m = fmaxf(lo, hi); cand = 2*j + ((hi > lo) ? 1 : 0);
            if (m > best1) { best1 = m; bk1 = cand; }
            asm("mov.b64 {%0, %1}, %2;" : "=f"(lo), "=f"(hi) : "l"(a2));
            m = fmaxf(lo, hi); cand = 2*j + ((hi > lo) ? 1 : 0);
            if (m > best2v) { best2v = m; bk2 = cand; }
            asm("mov.b64 {%0, %1}, %2;" : "=f"(lo), "=f"(hi) : "l"(a3));
            m = fmaxf(lo, hi); cand = 2*j + ((hi > lo) ? 1 : 0);
            if (m > best3) { best3 = m; bk3 = cand; }
        }
        int kk[4];
        kk[0] = combine4(best0, s*256 + bk0);
        kk[1] = combine4(best1, s*256 + bk1);
        kk[2] = combine4(best2v, s*256 + bk2);
        kk[3] = combine4(best3, s*256 + bk3);

        // gather chosen codeword from smem (split layout) + update residual
#pragma unroll
        for (int m = 0; m < 4; m++) {
            int k = kk[m];
            int base = ((k & 255) >> 1)*64 + ((k >> 8) << 2) + (k & 1);
            float ss = 0.f;
#pragma unroll
            for (int d = 0; d < 8; d++) {
                float ev = sE[base + (d >> 1)*16 + (d & 1)*2];
                float rlo;
                asm("mov.b64 {%0, _}, %1;" : "=f"(rlo) : "l"(r2[m][d]));
                float rn = rlo - ev;
                asm("mov.b64 %0, {%1, %1};" : "=l"(r2[m][d]) : "f"(rn));
                ss = fmaf(rn, rn, ss);
            }
            sse += ss;
        }
        if (s == 0) {
            float* oc = out_codes + (size_t)i*(G_*T_);
#pragma unroll
            for (int m = 0; m < 4; m++) oc[ofs[m]] = (float)kk[m];
        }
    }

    // q = zd - r_final; write zqd
    if (s == 0) {
        const float4* zd4 = (const float4*)g_zd;
        float4* zq4 = (float4*)g_zqd;
#pragma unroll
        for (int m = 0; m < 4; m++) {
            float4 lo = zd4[(size_t)(p0+m)*2], hi = zd4[(size_t)(p0+m)*2+1];
            float zv[8] = { lo.x, lo.y, lo.z, lo.w, hi.x, hi.y, hi.z, hi.w };
            float qv[8];
#pragma unroll
            for (int d = 0; d < 8; d++) {
                float rlo;
                asm("mov.b64 {%0, _}, %1;" : "=f"(rlo) : "l"(r2[m][d]));
                qv[d] = zv[d] - rlo;
            }
            zq4[(size_t)(p0+m)*2]   = make_float4(qv[0], qv[1], qv[2], qv[3]);
            zq4[(size_t)(p0+m)*2+1] = make_float4(qv[4], qv[5], qv[6], qv[7]);
        }
    }

    // loss partial (count each point once: s==0 lanes)
    float c = (s == 0) ? sse : 0.f;
#pragma unroll
    for (int off = 16; off > 0; off >>= 1)
        c += __shfl_down_sync(0xffffffffu, c, off);
    int lane = tid & 31, wid = tid >> 5;
    if (lane == 0) sWarp[wid] = c;
    __syncthreads();
    if (tid == 0) g_partial[bid] = sWarp[0] + sWarp[1];
}

// ---------------------------------------------------------------------------
// K4: proj_up fused with post_process (unchanged).
// ---------------------------------------------------------------------------
#define TT 25
__global__ void __launch_bounds__(256) k_up(const float* __restrict__ pu, float* __restrict__ out) {
    __shared__ float sZ[G_*TT*D_];
    int bid  = blockIdx.x;
    int b    = bid / (T_/TT);
    int tile = bid % (T_/TT);
    int t0   = tile * TT;
    int tid  = threadIdx.x;

    for (int idx = tid; idx < G_*TT*D_; idx += 256) {
        int g  = idx / (TT*D_);
        int rr = idx % (TT*D_);
        sZ[idx] = g_zqd[((size_t)g*NPG + b*T_ + t0)*D_ + rr];
    }
    __syncthreads();

    int wid = tid >> 5, lane = tid & 31;
    for (int task = wid; task < 48; task += 8) {
        int o   = task / 12;
        int rem = task % 12;
        int h   = rem >> 1;
        int ch  = rem & 1;
        int c   = ch*32 + lane;
        int pp  = o*FIX_ + c*6 + h;
        int g   = pp >> 9;
        const float4* pu4 = (const float4*)pu + (size_t)pp*2;
        float4 pl = __ldg(pu4), ph = __ldg(pu4 + 1);
        float* op = out + ((size_t)(b*H_ + h)*W_ + 4*t0 + o)*C_ + c;
        const float4* zb = (const float4*)(sZ + g*(TT*D_));
#pragma unroll 5
        for (int tl = 0; tl < TT; tl++) {
            float4 zl = zb[tl*2], zh = zb[tl*2 + 1];
            float s0 = zl.x*pl.x, s1 = zl.y*pl.y;
            s0 = fmaf(zl.z, pl.z, s0); s1 = fmaf(zl.w, pl.w, s1);
            s0 = fmaf(zh.x, ph.x, s0); s1 = fmaf(zh.y, ph.y, s1);
            s0 = fmaf(zh.z, ph.z, s0); s1 = fmaf(zh.w, ph.w, s1);
            op[(size_t)tl*4*C_] = s0 + s1;
        }
    }
}

// ---------------------------------------------------------------------------
// K5: final deterministic loss reduction.
// ---------------------------------------------------------------------------
__global__ void k_final(float* __restrict__ d_out) {
    __shared__ float s[512];
    int tid = threadIdx.x;
    float v = 0.f;
    for (int idx = tid; idx < RVQ_BLOCKS; idx += 512) v += g_partial[idx];
    s[tid] = v; __syncthreads();
    for (int off = 256; off > 0; off >>= 1) {
        if (tid < off) s[tid] += s[tid + off];
        __syncthreads();
    }
    if (tid == 0) {
        float loss = s[0] / (float)(G_ * B_ * T_ * D_);
        d_out[ZQ_SIZE + IDX_SIZE]     = loss;
        d_out[ZQ_SIZE + IDX_SIZE + 1] = loss;
    }
}

// ---------------------------------------------------------------------------
extern "C" void kernel_launch(void* const* d_in, const int* in_sizes, int n_in,
                              void* d_out, int out_size) {
    const float* z_e = (const float*)d_in[0];
    const float* pd  = (const float*)d_in[1];
    const float* pu  = (const float*)d_in[2];
    const float* cb  = (const float*)d_in[3];
    float* out = (float*)d_out;

    cudaFuncSetAttribute(k_down, cudaFuncAttributeMaxDynamicSharedMemorySize, K2_SMEM);

    k_norm<<<(G_*NVQ_*K_ + 255)/256, 256>>>(cb);
    k_down<<<B_*(T_/8), 256, K2_SMEM>>>(z_e, pd);
    k_rvq<<<RVQ_BLOCKS, 64>>>(out + ZQ_SIZE);
    k_up<<<B_*(T_/TT), 256>>>(pu, out);
    k_final<<<1, 512>>>(out);
}

// round 6
// speedup vs baseline: 2.5750x; 1.0004x over previous
#include <cuda_runtime.h>
#include <math.h>

#define B_    32
#define H_    6
#define W_    2400
#define C_    64
#define OV_   4
#define G_    3
#define NVQ_  6
#define K_    1024
#define D_    8
#define FIX_  384
#define GD_   512
#define T_    600
#define NPG   (B_*T_)              // 19200
#define NPTS  (G_*NPG)             // 57600
#define ZQ_SIZE  (B_*H_*W_*C_)     // 29491200
#define IDX_SIZE (B_*NVQ_*G_*T_)   // 345600
#define RVQ_BLOCKS 900             // 64 points per block, 64 threads

__device__ float g_en2s[G_*NVQ_*K_*D_];  // split layout [jl][q][s][pos]
__device__ float g_zd [G_*NPG*D_];
__device__ float g_zqd[G_*NPG*D_];
__device__ float g_partial[RVQ_BLOCKS];

// ---------------------------------------------------------------------------
// K1: normalize codebook rows, split layout:
// g_en2s[gi*8192 + jl*64 + (d>>1)*16 + s*4 + (d&1)*2 + half]
// ---------------------------------------------------------------------------
__global__ void k_norm(const float* __restrict__ cb) {
    int r = blockIdx.x * blockDim.x + threadIdx.x;
    if (r >= G_*NVQ_*K_) return;
    const float* src = cb + (size_t)r * D_;
    float v[8]; float ss = 0.f;
#pragma unroll
    for (int d = 0; d < 8; d++) { v[d] = src[d]; ss = fmaf(v[d], v[d], ss); }
    float inv = 1.0f / fmaxf(sqrtf(ss), 1e-12f);
    int gi = r >> 10, k = r & 1023;
    int s = k >> 8, jl = (k & 255) >> 1, half = k & 1;
    float* d2 = g_en2s + (size_t)gi*(K_*D_) + jl*64 + s*4 + half;
#pragma unroll
    for (int d = 0; d < 8; d++)
        d2[(d >> 1)*16 + (d & 1)*2] = v[d] * inv;
}

// ---------------------------------------------------------------------------
// K2: pre_process fused with proj_down. Staging pairs h planes -> STS.64
// (halves store wavefronts at the stride-24B scatter).
// ---------------------------------------------------------------------------
#define SZ_STRIDE 1540
#define PD_STRIDE 520
#define K2_SMEM   ((8*SZ_STRIDE + 24*PD_STRIDE) * 4)

__global__ void k_down(const float* __restrict__ ze, const float* __restrict__ pd) {
    extern __shared__ float sm[];
    float* sZ  = sm;
    float* sPD = sm + 8*SZ_STRIDE;
    int bid  = blockIdx.x;
    int b    = bid / (T_/8);
    int tblk = bid % (T_/8);
    int t0   = tblk * 8;
    int w0   = t0 * 4;
    int tid  = threadIdx.x;

    for (int idx = tid; idx < G_*D_*GD_; idx += 256) {
        int gd = idx >> 9, j = idx & 511;
        sPD[gd*PD_STRIDE + j] = pd[idx];
    }
#pragma unroll
    for (int hp = 0; hp < 3; hp++) {
        const float* s0 = ze + ((size_t)(b*H_ + 2*hp    )*W_ + w0) * C_;
        const float* s1 = ze + ((size_t)(b*H_ + 2*hp + 1)*W_ + w0) * C_;
        for (int e = tid; e < 32*64; e += 256) {
            float v0 = s0[e], v1 = s1[e];
            int wl = e >> 6, c = e & 63;
            int tl = wl >> 2, o = wl & 3;
            *(float2*)(sZ + tl*SZ_STRIDE + o*FIX_ + c*6 + 2*hp) = make_float2(v0, v1);
        }
    }
    __syncthreads();

    if (tid < 192) {
        int gd = tid >> 3;
        int tl = tid & 7;
        int g  = gd >> 3, d = gd & 7;
        const float4* zr = (const float4*)(sZ + tl*SZ_STRIDE + g*GD_);
        const float4* pr = (const float4*)(sPD + gd*PD_STRIDE);
        float a0 = 0.f, a1 = 0.f, a2 = 0.f, a3 = 0.f;
#pragma unroll 8
        for (int j = 0; j < 128; j += 2) {
            float4 z0 = zr[j],   p0 = pr[j];
            float4 z1 = zr[j+1], p1 = pr[j+1];
            a0 = fmaf(z0.x, p0.x, a0); a1 = fmaf(z0.y, p0.y, a1);
            a2 = fmaf(z0.z, p0.z, a2); a3 = fmaf(z0.w, p0.w, a3);
            a0 = fmaf(z1.x, p1.x, a0); a1 = fmaf(z1.y, p1.y, a1);
            a2 = fmaf(z1.z, p1.z, a2); a3 = fmaf(z1.w, p1.w, a3);
        }
        g_zd[((size_t)g*NPG + b*T_ + t0 + tl)*D_ + d] = (a0 + a1) + (a2 + a3);
    }
}

// ---------------------------------------------------------------------------
// K3: residual VQ. 64 thr = 16 slots x 4 splits, 4 points/thread.
// Hot loop tracks only (best value, pair index); even/odd resolved ONCE per
// stream per point by recomputing the winning pair (bit-identical ordering).
// ---------------------------------------------------------------------------
__device__ __forceinline__ int combine4(float best, int bk) {
    unsigned bits = __float_as_uint(best);
    unsigned su = bits ^ (unsigned)(((int)bits >> 31) | 0x80000000);
    unsigned long long key = ((unsigned long long)su << 10) | (unsigned)(1023 - bk);
    unsigned long long o = __shfl_xor_sync(0xffffffffu, key, 1);
    key = (o > key) ? o : key;
    o = __shfl_xor_sync(0xffffffffu, key, 2);
    key = (o > key) ? o : key;
    return 1023 - (int)(key & 1023u);
}

__global__ void __launch_bounds__(64) k_rvq(float* __restrict__ out_codes) {
    __shared__ float sE[K_*D_];   // 32 KB
    __shared__ float sWarp[2];
    int bid = blockIdx.x;
    int g   = bid / (RVQ_BLOCKS/G_);
    int lb  = bid % (RVQ_BLOCKS/G_);
    int tid = threadIdx.x;
    int pp  = tid >> 2;
    int s   = tid & 3;
    int pl0 = lb*64 + pp*4;
    int p0  = g*NPG + pl0;

    unsigned long long r2[4][8];
    {
        const float4* zd4 = (const float4*)g_zd;
#pragma unroll
        for (int m = 0; m < 4; m++) {
            float4 lo = zd4[(size_t)(p0+m)*2], hi = zd4[(size_t)(p0+m)*2+1];
            float rv[8] = { lo.x, lo.y, lo.z, lo.w, hi.x, hi.y, hi.z, hi.w };
#pragma unroll
            for (int d = 0; d < 8; d++)
                asm("mov.b64 %0, {%1, %1};" : "=l"(r2[m][d]) : "f"(rv[d]));
        }
    }
    int ofs[4];
#pragma unroll
    for (int m = 0; m < 4; m++) {
        int pl = pl0 + m;
        int b = pl / T_, t = pl - b*T_;
        ofs[m] = (b*NVQ_*G_ + g)*T_ + t;
    }

    float sse = 0.f;

    for (int i = 0; i < NVQ_; i++) {
        __syncthreads();
        {
            const float4* src = (const float4*)(g_en2s + (size_t)(g*NVQ_ + i)*(K_*D_));
            float4* dst = (float4*)sE;
#pragma unroll
            for (int j = 0; j < 32; j++) dst[tid + j*64] = src[tid + j*64];
        }
        __syncthreads();

        const ulonglong2* e2 = (const ulonglong2*)sE;
        float best[4] = { -3.0e38f, -3.0e38f, -3.0e38f, -3.0e38f };
        int   bj[4]   = { 0, 0, 0, 0 };
#pragma unroll 2
        for (int j = 0; j < 128; j++) {
            int base = j*16 + s;
            ulonglong2 c0 = e2[base];
            ulonglong2 c1 = e2[base + 4];
            ulonglong2 c2 = e2[base + 8];
            ulonglong2 c3 = e2[base + 12];
#define SIM(mm, ACC) \
            asm("mul.rn.f32x2 %0, %1, %2;"     : "=l"(ACC) : "l"(r2[mm][0]), "l"(c0.x)); \
            asm("fma.rn.f32x2 %0, %1, %2, %0;" : "+l"(ACC) : "l"(r2[mm][1]), "l"(c0.y)); \
            asm("fma.rn.f32x2 %0, %1, %2, %0;" : "+l"(ACC) : "l"(r2[mm][2]), "l"(c1.x)); \
            asm("fma.rn.f32x2 %0, %1, %2, %0;" : "+l"(ACC) : "l"(r2[mm][3]), "l"(c1.y)); \
            asm("fma.rn.f32x2 %0, %1, %2, %0;" : "+l"(ACC) : "l"(r2[mm][4]), "l"(c2.x)); \
            asm("fma.rn.f32x2 %0, %1, %2, %0;" : "+l"(ACC) : "l"(r2[mm][5]), "l"(c2.y)); \
            asm("fma.rn.f32x2 %0, %1, %2, %0;" : "+l"(ACC) : "l"(r2[mm][6]), "l"(c3.x)); \
            asm("fma.rn.f32x2 %0, %1, %2, %0;" : "+l"(ACC) : "l"(r2[mm][7]), "l"(c3.y));
            unsigned long long a0, a1, a2, a3;
            SIM(0, a0) SIM(1, a1) SIM(2, a2) SIM(3, a3)
            float lo, hi, m;
            asm("mov.b64 {%0, %1}, %2;" : "=f"(lo), "=f"(hi) : "l"(a0));
            m = fmaxf(lo, hi);
            if (m > best[0]) { best[0] = m; bj[0] = j; }
            asm("mov.b64 {%0, %1}, %2;" : "=f"(lo), "=f"(hi) : "l"(a1));
            m = fmaxf(lo, hi);
            if (m > best[1]) { best[1] = m; bj[1] = j; }
            asm("mov.b64 {%0, %1}, %2;" : "=f"(lo), "=f"(hi) : "l"(a2));
            m = fmaxf(lo, hi);
            if (m > best[2]) { best[2] = m; bj[2] = j; }
            asm("mov.b64 {%0, %1}, %2;" : "=f"(lo), "=f"(hi) : "l"(a3));
            m = fmaxf(lo, hi);
            if (m > best[3]) { best[3] = m; bj[3] = j; }
        }

        // resolve even/odd by recomputing the winning pair (same op order)
        int kk[4];
#pragma unroll
        for (int m = 0; m < 4; m++) {
            int base = bj[m]*16 + s;
            ulonglong2 c0 = e2[base];
            ulonglong2 c1 = e2[base + 4];
            ulonglong2 c2 = e2[base + 8];
            ulonglong2 c3 = e2[base + 12];
            unsigned long long a;
            switch (m) {
                case 0: { SIM(0, a) } break;
                case 1: { SIM(1, a) } break;
                case 2: { SIM(2, a) } break;
                default:{ SIM(3, a) } break;
            }
            float lo, hi;
            asm("mov.b64 {%0, %1}, %2;" : "=f"(lo), "=f"(hi) : "l"(a));
            int kc = s*256 + 2*bj[m] + ((hi > lo) ? 1 : 0);
            kk[m] = combine4(best[m], kc);
        }
#undef SIM

        // gather chosen codeword from smem + update residual
#pragma unroll
        for (int m = 0; m < 4; m++) {
            int k = kk[m];
            int base = ((k & 255) >> 1)*64 + ((k >> 8) << 2) + (k & 1);
            float ss = 0.f;
#pragma unroll
            for (int d = 0; d < 8; d++) {
                float ev = sE[base + (d >> 1)*16 + (d & 1)*2];
                float rlo;
                asm("mov.b64 {%0, _}, %1;" : "=f"(rlo) : "l"(r2[m][d]));
                float rn = rlo - ev;
                asm("mov.b64 %0, {%1, %1};" : "=l"(r2[m][d]) : "f"(rn));
                ss = fmaf(rn, rn, ss);
            }
            sse += ss;
        }
        if (s == 0) {
            float* oc = out_codes + (size_t)i*(G_*T_);
#pragma unroll
            for (int m = 0; m < 4; m++) oc[ofs[m]] = (float)kk[m];
        }
    }

    if (s == 0) {
        const float4* zd4 = (const float4*)g_zd;
        float4* zq4 = (float4*)g_zqd;
#pragma unroll
        for (int m = 0; m < 4; m++) {
            float4 lo = zd4[(size_t)(p0+m)*2], hi = zd4[(size_t)(p0+m)*2+1];
            float zv[8] = { lo.x, lo.y, lo.z, lo.w, hi.x, hi.y, hi.z, hi.w };
            float qv[8];
#pragma unroll
            for (int d = 0; d < 8; d++) {
                float rlo;
                asm("mov.b64 {%0, _}, %1;" : "=f"(rlo) : "l"(r2[m][d]));
                qv[d] = zv[d] - rlo;
            }
            zq4[(size_t)(p0+m)*2]   = make_float4(qv[0], qv[1], qv[2], qv[3]);
            zq4[(size_t)(p0+m)*2+1] = make_float4(qv[4], qv[5], qv[6], qv[7]);
        }
    }

    float c = (s == 0) ? sse : 0.f;
#pragma unroll
    for (int off = 16; off > 0; off >>= 1)
        c += __shfl_down_sync(0xffffffffu, c, off);
    int lane = tid & 31, wid = tid >> 5;
    if (lane == 0) sWarp[wid] = c;
    __syncthreads();
    if (tid == 0) g_partial[bid] = sWarp[0] + sWarp[1];
}

// ---------------------------------------------------------------------------
// K4: proj_up fused with post_process. 2 consecutive c per thread, STG.64.
// ---------------------------------------------------------------------------
#define TT 25
__global__ void __launch_bounds__(256) k_up(const float* __restrict__ pu, float* __restrict__ out) {
    __shared__ float sZ[G_*TT*D_];
    int bid  = blockIdx.x;
    int b    = bid / (T_/TT);
    int tile = bid % (T_/TT);
    int t0   = tile * TT;
    int tid  = threadIdx.x;

    for (int idx = tid; idx < G_*TT*D_; idx += 256) {
        int g  = idx / (TT*D_);
        int rr = idx % (TT*D_);
        sZ[idx] = g_zqd[((size_t)g*NPG + b*T_ + t0)*D_ + rr];
    }
    __syncthreads();

    int wid = tid >> 5, lane = tid & 31;
#pragma unroll
    for (int task = wid; task < 24; task += 8) {
        int o = task >> 3;       // tasks 0..23 cover o in 0..2; o=3 handled below? NO:
        // 24 tasks = (o,h): o = task/6, h = task%6
        o = task / 6;
        int h = task % 6;
        int c0 = 2*lane, c1 = 2*lane + 1;
        int pp0 = o*FIX_ + c0*6 + h;
        int pp1 = pp0 + 6;
        int g0 = pp0 >> 9, g1 = pp1 >> 9;
        const float4* puA = (const float4*)pu + (size_t)pp0*2;
        const float4* puB = (const float4*)pu + (size_t)pp1*2;
        float4 pl0 = __ldg(puA), ph0 = __ldg(puA + 1);
        float4 pl1 = __ldg(puB), ph1 = __ldg(puB + 1);
        float2* op = (float2*)(out + ((size_t)(b*H_ + h)*W_ + 4*t0 + o)*C_ + c0);
        const float4* zb0 = (const float4*)(sZ + g0*(TT*D_));
        const float4* zb1 = (const float4*)(sZ + g1*(TT*D_));
        if (g0 == g1) {
#pragma unroll 5
            for (int tl = 0; tl < TT; tl++) {
                float4 zl = zb0[tl*2], zh = zb0[tl*2 + 1];
                float s0 = zl.x*pl0.x, s1 = zl.y*pl0.y;
                s0 = fmaf(zl.z, pl0.z, s0); s1 = fmaf(zl.w, pl0.w, s1);
                s0 = fmaf(zh.x, ph0.x, s0); s1 = fmaf(zh.y, ph0.y, s1);
                s0 = fmaf(zh.z, ph0.z, s0); s1 = fmaf(zh.w, ph0.w, s1);
                float u0 = zl.x*pl1.x, u1 = zl.y*pl1.y;
                u0 = fmaf(zl.z, pl1.z, u0); u1 = fmaf(zl.w, pl1.w, u1);
                u0 = fmaf(zh.x, ph1.x, u0); u1 = fmaf(zh.y, ph1.y, u1);
                u0 = fmaf(zh.z, ph1.z, u0); u1 = fmaf(zh.w, ph1.w, u1);
                op[(size_t)tl*2*C_] = make_float2(s0 + s1, u0 + u1);
            }
        } else {
#pragma unroll 5
            for (int tl = 0; tl < TT; tl++) {
                float4 zl = zb0[tl*2], zh = zb0[tl*2 + 1];
                float s0 = zl.x*pl0.x, s1 = zl.y*pl0.y;
                s0 = fmaf(zl.z, pl0.z, s0); s1 = fmaf(zl.w, pl0.w, s1);
                s0 = fmaf(zh.x, ph0.x, s0); s1 = fmaf(zh.y, ph0.y, s1);
                s0 = fmaf(zh.z, ph0.z, s0); s1 = fmaf(zh.w, ph0.w, s1);
                float4 yl = zb1[tl*2], yh = zb1[tl*2 + 1];
                float u0 = yl.x*pl1.x, u1 = yl.y*pl1.y;
                u0 = fmaf(yl.z, pl1.z, u0); u1 = fmaf(yl.w, pl1.w, u1);
                u0 = fmaf(yh.x, ph1.x, u0); u1 = fmaf(yh.y, ph1.y, u1);
                u0 = fmaf(yh.z, ph1.z, u0); u1 = fmaf(yh.w, ph1.w, u1);
                op[(size_t)tl*2*C_] = make_float2(s0 + s1, u0 + u1);
            }
        }
    }
}

// ---------------------------------------------------------------------------
// K5: final deterministic loss reduction.
// ---------------------------------------------------------------------------
__global__ void k_final(float* __restrict__ d_out) {
    __shared__ float s[512];
    int tid = threadIdx.x;
    float v = 0.f;
    for (int idx = tid; idx < RVQ_BLOCKS; idx += 512) v += g_partial[idx];
    s[tid] = v; __syncthreads();
    for (int off = 256; off > 0; off >>= 1) {
        if (tid < off) s[tid] += s[tid + off];
        __syncthreads();
    }
    if (tid == 0) {
        float loss = s[0] / (float)(G_ * B_ * T_ * D_);
        d_out[ZQ_SIZE + IDX_SIZE]     = loss;
        d_out[ZQ_SIZE + IDX_SIZE + 1] = loss;
    }
}

// ---------------------------------------------------------------------------
extern "C" void kernel_launch(void* const* d_in, const int* in_sizes, int n_in,
                              void* d_out, int out_size) {
    const float* z_e = (const float*)d_in[0];
    const float* pd  = (const float*)d_in[1];
    const float* pu  = (const float*)d_in[2];
    const float* cb  = (const float*)d_in[3];
    float* out = (float*)d_out;

    cudaFuncSetAttribute(k_down, cudaFuncAttributeMaxDynamicSharedMemorySize, K2_SMEM);

    k_norm<<<(G_*NVQ_*K_ + 255)/256, 256>>>(cb);
    k_down<<<B_*(T_/8), 256, K2_SMEM>>>(z_e, pd);
    k_rvq<<<RVQ_BLOCKS, 64>>>(out + ZQ_SIZE);
    k_up<<<B_*(T_/TT), 256>>>(pu, out);
    k_final<<<1, 512>>>(out);
}